// round 4
// baseline (speedup 1.0000x reference)
#include <cuda_runtime.h>
#include <cuda_bf16.h>
#include <math.h>
#include <stdint.h>

// x:        [4, 256, 64, 64]  -> [b][c][n], n = 4096
// gn_weight [256], gn_bias [256]
// w_qkv     [384, 256]
// w_out     [256, 128]
// b_out     [256]
// out       [4, 256, 64, 64]

#define NB    4
#define NC    256
#define NTOK  4096
#define NHEAD 4
#define DH    32
#define HID   128
#define NQKV  384
#define NGRP  32
#define CPG   8

// -------- scratch --------
__device__ float g_qkv[(size_t)NB * NQKV * NTOK];   // [b][o][n]
__device__ float g_att[(size_t)NB * HID * NTOK];    // [b][h*32+f][n]
__device__ float g_alpha[NB * NC];
__device__ float g_beta[NB * NC];

// ---------- helpers ----------
__device__ __forceinline__ uint32_t f2tf(float f) {
    uint32_t u; asm("cvt.rna.tf32.f32 %0, %1;" : "=r"(u) : "f"(f)); return u;
}
__device__ __forceinline__ float ex2(float x) {
    float y; asm("ex2.approx.ftz.f32 %0, %1;" : "=f"(y) : "f"(x)); return y;
}
__device__ __forceinline__ void mma_tf32(float c[4], const uint32_t a[4], uint32_t b0, uint32_t b1) {
    asm volatile("mma.sync.aligned.m16n8k8.row.col.f32.tf32.tf32.f32 "
                 "{%0,%1,%2,%3}, {%4,%5,%6,%7}, {%8,%9}, {%0,%1,%2,%3};"
                 : "+f"(c[0]), "+f"(c[1]), "+f"(c[2]), "+f"(c[3])
                 : "r"(a[0]), "r"(a[1]), "r"(a[2]), "r"(a[3]), "r"(b0), "r"(b1));
}
__device__ __forceinline__ void cpa16(uint32_t dst, const void* src) {
    asm volatile("cp.async.ca.shared.global [%0], [%1], 16;" :: "r"(dst), "l"(src));
}
#define CPA_COMMIT() asm volatile("cp.async.commit_group;")

// ================= GroupNorm stats =================
__global__ void __launch_bounds__(256) k_gnstats(const float* __restrict__ x,
                                                 const float* __restrict__ gw,
                                                 const float* __restrict__ gb)
{
    const int b = blockIdx.x >> 5;
    const int g = blockIdx.x & 31;
    const float4* p4 = (const float4*)(x + ((size_t)(b * NC + g * CPG)) * NTOK);
    float s = 0.f, s2 = 0.f;
    for (int i = threadIdx.x; i < 8192; i += 256) {
        float4 v = p4[i];
        s  += (v.x + v.y) + (v.z + v.w);
        s2 += v.x * v.x + v.y * v.y + v.z * v.z + v.w * v.w;
    }
    #pragma unroll
    for (int off = 16; off; off >>= 1) {
        s  += __shfl_xor_sync(0xffffffffu, s,  off);
        s2 += __shfl_xor_sync(0xffffffffu, s2, off);
    }
    __shared__ float ws[8], ws2[8];
    __shared__ float sm, sr;
    const int w = threadIdx.x >> 5;
    if ((threadIdx.x & 31) == 0) { ws[w] = s; ws2[w] = s2; }
    __syncthreads();
    if (threadIdx.x == 0) {
        float t = 0.f, t2 = 0.f;
        #pragma unroll
        for (int i = 0; i < 8; i++) { t += ws[i]; t2 += ws2[i]; }
        float mean = t * (1.f / 32768.f);
        float var  = t2 * (1.f / 32768.f) - mean * mean;
        sm = mean;
        sr = rsqrtf(var + 1e-5f);
    }
    __syncthreads();
    if (threadIdx.x < CPG) {
        int c = g * CPG + threadIdx.x;
        float a = gw[c] * sr;
        g_alpha[b * NC + c] = a;
        g_beta [b * NC + c] = gb[c] - sm * a;
    }
}

// ================= tf32 tensor-core GEMM =================
// C[b][m][n] = sum_k A[m][k] * B[b][k][n] (+bias[m]) ; optional per-(b,k) affine on B.
// Block: 256 thr, tile 128m x 64n, 8 warps (4m x 2n), warp 32x32, k-chunk 32.
template<int MTOT, int KTOT, bool AFFINE, bool BIASED>
__global__ void __launch_bounds__(256) k_gemm(const float* __restrict__ A,
                                              const float* __restrict__ Bg,
                                              float* __restrict__ Cg,
                                              const float* __restrict__ bias)
{
    const int b  = blockIdx.z;
    const int m0 = blockIdx.y * 128;
    const int n0 = blockIdx.x * 64;
    __shared__ float Ws[128][36];   // [m][k] pad 36: A-frag reads conflict-free
    __shared__ float Xs[32][72];    // [k][n] pad 72: B-frag reads conflict-free
    const float* Bb = Bg + (size_t)b * KTOT * NTOK;
    const float* al = AFFINE ? (g_alpha + b * NC) : nullptr;
    const float* be = AFFINE ? (g_beta  + b * NC) : nullptr;

    const int tid  = threadIdx.x;
    const int w    = tid >> 5;
    const int lane = tid & 31;
    const int g    = lane >> 2;
    const int t    = lane & 3;
    const int wm   = (w >> 1) * 32;
    const int wn   = (w & 1) * 32;

    float acc[2][4][4] = {};

    for (int k0 = 0; k0 < KTOT; k0 += 32) {
        __syncthreads();
        #pragma unroll
        for (int i = 0; i < 4; i++) {                // A tile 128x32
            int idx4 = tid + 256 * i;
            int r = idx4 >> 3, c = (idx4 & 7) << 2;
            float4 v = *(const float4*)(A + (size_t)(m0 + r) * KTOT + k0 + c);
            Ws[r][c + 0] = __uint_as_float(f2tf(v.x));
            Ws[r][c + 1] = __uint_as_float(f2tf(v.y));
            Ws[r][c + 2] = __uint_as_float(f2tf(v.z));
            Ws[r][c + 3] = __uint_as_float(f2tf(v.w));
        }
        #pragma unroll
        for (int i = 0; i < 2; i++) {                // B tile 32x64
            int idx4 = tid + 256 * i;
            int kc = idx4 >> 4, nc = (idx4 & 15) << 2;
            float4 v = *(const float4*)(Bb + (size_t)(k0 + kc) * NTOK + n0 + nc);
            if (AFFINE) {
                float a = al[k0 + kc], bb = be[k0 + kc];
                v.x = fmaf(v.x, a, bb); v.y = fmaf(v.y, a, bb);
                v.z = fmaf(v.z, a, bb); v.w = fmaf(v.w, a, bb);
            }
            Xs[kc][nc + 0] = __uint_as_float(f2tf(v.x));
            Xs[kc][nc + 1] = __uint_as_float(f2tf(v.y));
            Xs[kc][nc + 2] = __uint_as_float(f2tf(v.z));
            Xs[kc][nc + 3] = __uint_as_float(f2tf(v.w));
        }
        __syncthreads();
        #pragma unroll
        for (int ks = 0; ks < 4; ks++) {
            uint32_t a[2][4];
            #pragma unroll
            for (int mf = 0; mf < 2; mf++) {
                int r = wm + 16 * mf + g;
                a[mf][0] = __float_as_uint(Ws[r    ][8 * ks + t]);
                a[mf][1] = __float_as_uint(Ws[r + 8][8 * ks + t]);
                a[mf][2] = __float_as_uint(Ws[r    ][8 * ks + t + 4]);
                a[mf][3] = __float_as_uint(Ws[r + 8][8 * ks + t + 4]);
            }
            #pragma unroll
            for (int nf = 0; nf < 4; nf++) {
                uint32_t b0 = __float_as_uint(Xs[8 * ks + t    ][wn + 8 * nf + g]);
                uint32_t b1 = __float_as_uint(Xs[8 * ks + t + 4][wn + 8 * nf + g]);
                mma_tf32(acc[0][nf], a[0], b0, b1);
                mma_tf32(acc[1][nf], a[1], b0, b1);
            }
        }
    }

    float* Cb = Cg + (size_t)b * MTOT * NTOK;
    #pragma unroll
    for (int mf = 0; mf < 2; mf++) {
        int row = m0 + wm + 16 * mf + g;
        float bv0 = BIASED ? bias[row]     : 0.f;
        float bv8 = BIASED ? bias[row + 8] : 0.f;
        #pragma unroll
        for (int nf = 0; nf < 4; nf++) {
            int col = n0 + wn + 8 * nf + 2 * t;
            *(float2*)(Cb + (size_t)row * NTOK + col) =
                make_float2(acc[mf][nf][0] + bv0, acc[mf][nf][1] + bv0);
            *(float2*)(Cb + (size_t)(row + 8) * NTOK + col) =
                make_float2(acc[mf][nf][2] + bv8, acc[mf][nf][3] + bv8);
        }
    }
}

// ================= Flash attention: tf32 mma + cp.async double buffer =================
#define QT 128
#define KT 64
// SMEM union layout (bytes):
//  Ks0 @ 0      : 32*72*4 = 9216
//  Vs0 @ 9216   : 32*68*4 = 8704
//  Ks1 @ 17920  : 9216
//  Vs1 @ 27136  : 8704     -> total 35840
//  Qs  @ 0      : 128*36*4 = 18432 (staging only; aliased, temporally separated)
#define SM_BYTES 35840
__global__ void __launch_bounds__(256, 2) k_attn()
{
    __shared__ __align__(16) char smraw[SM_BYTES];
    uint32_t (*Qs)[36] = (uint32_t(*)[36])smraw;
    uint32_t (*KsBuf[2])[72];
    uint32_t (*VsBuf[2])[68];
    KsBuf[0] = (uint32_t(*)[72])(smraw);
    VsBuf[0] = (uint32_t(*)[68])(smraw + 9216);
    KsBuf[1] = (uint32_t(*)[72])(smraw + 17920);
    VsBuf[1] = (uint32_t(*)[68])(smraw + 27136);
    const uint32_t smbase = (uint32_t)__cvta_generic_to_shared(smraw);

    const int b  = blockIdx.z, h = blockIdx.y;
    const int n0 = blockIdx.x * QT;
    const int tid  = threadIdx.x;
    const int w    = tid >> 5;
    const int lane = tid & 31;
    const int grp  = lane >> 2;
    const int tg   = lane & 3;
    const int par  = lane & 1;
    const int srcA = (lane & ~3) | (tg >> 1);
    const int srcB = srcA | 2;

    const float* qb = g_qkv + ((size_t)b * NQKV + h * DH) * NTOK;
    const float* kb = qb + (size_t)HID * NTOK;
    const float* vb = qb + (size_t)2 * HID * NTOK;

    const float qscale = 0.17677669529663687f * 1.4426950408889634f; // SCALE*log2(e)

    // ---- stage Q (transpose + scale + rna-cvt) ----
    #pragma unroll
    for (int i = 0; i < 4; i++) {
        int idx4 = tid + 256 * i;
        int f  = idx4 >> 5;
        int nc = (idx4 & 31) << 2;
        float4 v = *(const float4*)(qb + (size_t)f * NTOK + n0 + nc);
        Qs[nc + 0][f] = f2tf(v.x * qscale);
        Qs[nc + 1][f] = f2tf(v.y * qscale);
        Qs[nc + 2][f] = f2tf(v.z * qscale);
        Qs[nc + 3][f] = f2tf(v.w * qscale);
    }
    __syncthreads();

    const int qrow = w * 16 + grp;
    uint32_t qa[4][4];
    #pragma unroll
    for (int ks = 0; ks < 4; ks++) {
        qa[ks][0] = Qs[qrow    ][ks * 8 + tg];
        qa[ks][1] = Qs[qrow + 8][ks * 8 + tg];
        qa[ks][2] = Qs[qrow    ][ks * 8 + tg + 4];
        qa[ks][3] = Qs[qrow + 8][ks * 8 + tg + 4];
    }
    __syncthreads();   // qa reads done before K/V overwrite the aliased region

    // per-thread staging coords (raw f32 bits; tf32 mma truncates mantissa in HW)
    const int sf0 = tid >> 4;              // 0..15
    const int sj0 = (tid & 15) << 2;       // 0..60
    const int sf1 = sf0 + 16;              // 16..31
    const uint32_t kd0 = (uint32_t)(sf0 * 72 + sj0) * 4;
    const uint32_t kd1 = (uint32_t)(sf1 * 72 + sj0) * 4;
    const uint32_t vd0 = 9216u  + (uint32_t)(sf0 * 68 + sj0) * 4;
    const uint32_t vd1 = 9216u  + (uint32_t)(sf1 * 68 + sj0) * 4;

    float o[4][4] = {};
    float m0r = -1e30f, m1r = -1e30f;
    float l0 = 0.f, l1 = 0.f;

    // prefetch tile 0 into buf 0
    {
        cpa16(smbase + kd0, kb + (size_t)sf0 * NTOK + sj0);
        cpa16(smbase + kd1, kb + (size_t)sf1 * NTOK + sj0);
        cpa16(smbase + vd0, vb + (size_t)sf0 * NTOK + sj0);
        cpa16(smbase + vd1, vb + (size_t)sf1 * NTOK + sj0);
        CPA_COMMIT();
    }

    for (int tIdx = 0; tIdx < NTOK / KT; tIdx++) {
        const int cur = tIdx & 1;
        if (tIdx + 1 < NTOK / KT) {
            const uint32_t boff = smbase + (cur ? 0u : 17920u);
            const int j0n = (tIdx + 1) * KT;
            cpa16(boff + kd0, kb + (size_t)sf0 * NTOK + j0n + sj0);
            cpa16(boff + kd1, kb + (size_t)sf1 * NTOK + j0n + sj0);
            cpa16(boff + vd0, vb + (size_t)sf0 * NTOK + j0n + sj0);
            cpa16(boff + vd1, vb + (size_t)sf1 * NTOK + j0n + sj0);
            CPA_COMMIT();
            asm volatile("cp.async.wait_group 1;");
        } else {
            asm volatile("cp.async.wait_group 0;");
        }
        __syncthreads();

        uint32_t (*Ks)[72] = KsBuf[cur];
        uint32_t (*Vs)[68] = VsBuf[cur];

        // ---- S = Q K^T ----
        float sc[8][4];
        #pragma unroll
        for (int nt = 0; nt < 8; nt++) {
            sc[nt][0] = sc[nt][1] = sc[nt][2] = sc[nt][3] = 0.f;
            #pragma unroll
            for (int ks = 0; ks < 4; ks++) {
                uint32_t b0 = Ks[ks * 8 + tg    ][nt * 8 + grp];
                uint32_t b1 = Ks[ks * 8 + tg + 4][nt * 8 + grp];
                mma_tf32(sc[nt], qa[ks], b0, b1);
            }
        }

        // ---- online softmax (exp2 domain) ----
        float mt0 = -1e30f, mt1 = -1e30f;
        #pragma unroll
        for (int nt = 0; nt < 8; nt++) {
            mt0 = fmaxf(mt0, fmaxf(sc[nt][0], sc[nt][1]));
            mt1 = fmaxf(mt1, fmaxf(sc[nt][2], sc[nt][3]));
        }
        mt0 = fmaxf(mt0, __shfl_xor_sync(0xffffffffu, mt0, 1));
        mt0 = fmaxf(mt0, __shfl_xor_sync(0xffffffffu, mt0, 2));
        mt1 = fmaxf(mt1, __shfl_xor_sync(0xffffffffu, mt1, 1));
        mt1 = fmaxf(mt1, __shfl_xor_sync(0xffffffffu, mt1, 2));

        float mn0 = fmaxf(m0r, mt0), mn1 = fmaxf(m1r, mt1);
        float c0 = ex2(m0r - mn0), c1 = ex2(m1r - mn1);
        m0r = mn0; m1r = mn1;
        l0 *= c0; l1 *= c1;
        #pragma unroll
        for (int nf = 0; nf < 4; nf++) {
            o[nf][0] *= c0; o[nf][1] *= c0;
            o[nf][2] *= c1; o[nf][3] *= c1;
        }

        float rs0 = 0.f, rs1 = 0.f;
        #pragma unroll
        for (int nt = 0; nt < 8; nt++) {
            float p0 = ex2(sc[nt][0] - mn0);
            float p1 = ex2(sc[nt][1] - mn0);
            float p2 = ex2(sc[nt][2] - mn1);
            float p3 = ex2(sc[nt][3] - mn1);
            rs0 += p0 + p1; rs1 += p2 + p3;
            sc[nt][0] = p0; sc[nt][1] = p1; sc[nt][2] = p2; sc[nt][3] = p3;
        }
        rs0 += __shfl_xor_sync(0xffffffffu, rs0, 1);
        rs0 += __shfl_xor_sync(0xffffffffu, rs0, 2);
        rs1 += __shfl_xor_sync(0xffffffffu, rs1, 1);
        rs1 += __shfl_xor_sync(0xffffffffu, rs1, 2);
        l0 += rs0; l1 += rs1;

        // ---- O += P V (P redistributed via shuffles; raw bits as tf32) ----
        #pragma unroll
        for (int kk = 0; kk < 8; kk++) {
            uint32_t u0A = __shfl_sync(0xffffffffu, __float_as_uint(sc[kk][0]), srcA);
            uint32_t u1A = __shfl_sync(0xffffffffu, __float_as_uint(sc[kk][1]), srcA);
            uint32_t u2A = __shfl_sync(0xffffffffu, __float_as_uint(sc[kk][2]), srcA);
            uint32_t u3A = __shfl_sync(0xffffffffu, __float_as_uint(sc[kk][3]), srcA);
            uint32_t u0B = __shfl_sync(0xffffffffu, __float_as_uint(sc[kk][0]), srcB);
            uint32_t u1B = __shfl_sync(0xffffffffu, __float_as_uint(sc[kk][1]), srcB);
            uint32_t u2B = __shfl_sync(0xffffffffu, __float_as_uint(sc[kk][2]), srcB);
            uint32_t u3B = __shfl_sync(0xffffffffu, __float_as_uint(sc[kk][3]), srcB);
            uint32_t pa[4];
            pa[0] = par ? u1A : u0A;
            pa[1] = par ? u3A : u2A;
            pa[2] = par ? u1B : u0B;
            pa[3] = par ? u3B : u2B;
            #pragma unroll
            for (int nf = 0; nf < 4; nf++) {
                uint32_t b0 = Vs[nf * 8 + grp][kk * 8 + tg];
                uint32_t b1 = Vs[nf * 8 + grp][kk * 8 + tg + 4];
                mma_tf32(o[nf], pa, b0, b1);
            }
        }
        __syncthreads();   // all reads of buf[cur] done before it is re-staged
    }

    // ---- epilogue: normalize, stage via SMEM (reuse Qs region), coalesced write ----
    float inv0 = 1.0f / l0, inv1 = 1.0f / l1;
    #pragma unroll
    for (int nf = 0; nf < 4; nf++) {
        Qs[qrow    ][nf * 8 + 2 * tg    ] = __float_as_uint(o[nf][0] * inv0);
        Qs[qrow    ][nf * 8 + 2 * tg + 1] = __float_as_uint(o[nf][1] * inv0);
        Qs[qrow + 8][nf * 8 + 2 * tg    ] = __float_as_uint(o[nf][2] * inv1);
        Qs[qrow + 8][nf * 8 + 2 * tg + 1] = __float_as_uint(o[nf][3] * inv1);
    }
    __syncthreads();
    float* ob = g_att + ((size_t)b * HID + h * DH) * NTOK;
    #pragma unroll
    for (int i = 0; i < 4; i++) {
        int idx4 = tid + 256 * i;
        int f  = idx4 >> 5;
        int nc = (idx4 & 31) << 2;
        float4 v = make_float4(__uint_as_float(Qs[nc + 0][f]),
                               __uint_as_float(Qs[nc + 1][f]),
                               __uint_as_float(Qs[nc + 2][f]),
                               __uint_as_float(Qs[nc + 3][f]));
        *(float4*)(ob + (size_t)f * NTOK + n0 + nc) = v;
    }
}

// ================= launch =================
extern "C" void kernel_launch(void* const* d_in, const int* in_sizes, int n_in,
                              void* d_out, int out_size)
{
    const float* x    = (const float*)d_in[0];
    const float* gw   = (const float*)d_in[1];
    const float* gb   = (const float*)d_in[2];
    const float* wqkv = (const float*)d_in[3];
    const float* wout = (const float*)d_in[4];
    const float* bout = (const float*)d_in[5];
    float* out = (float*)d_out;

    float* qkv = nullptr; cudaGetSymbolAddress((void**)&qkv, g_qkv);
    float* att = nullptr; cudaGetSymbolAddress((void**)&att, g_att);

    k_gnstats<<<NB * NGRP, 256>>>(x, gw, gb);
    k_gemm<NQKV, NC, true, false><<<dim3(64, 3, NB), 256>>>(wqkv, x, qkv, nullptr);
    k_attn<<<dim3(NTOK / QT, NHEAD, NB), 256>>>();
    k_gemm<NC, HID, false, true><<<dim3(64, 2, NB), 256>>>(wout, att, out, bout);
}

// round 5
// speedup vs baseline: 1.1958x; 1.1958x over previous
#include <cuda_runtime.h>
#include <cuda_bf16.h>
#include <math.h>
#include <stdint.h>

#define NB    4
#define NC    256
#define NTOK  4096
#define NHEAD 4
#define DH    32
#define HID   128
#define NQKV  384
#define CPG   8

// -------- scratch --------
__device__ float g_qkv[(size_t)NB * NQKV * NTOK];   // [b][o][n]  rna-tf32 values
__device__ float g_att[(size_t)NB * HID * NTOK];    // [b][h*32+f][n] rna-tf32 values
__device__ float g_xn [(size_t)NB * NC * NTOK];     // normalized x, rna-tf32

// ---------- helpers ----------
__device__ __forceinline__ uint32_t f2tf(float f) {
    uint32_t u; asm("cvt.rna.tf32.f32 %0, %1;" : "=r"(u) : "f"(f)); return u;
}
__device__ __forceinline__ float rtf(float f) { return __uint_as_float(f2tf(f)); }
__device__ __forceinline__ float ex2(float x) {
    float y; asm("ex2.approx.ftz.f32 %0, %1;" : "=f"(y) : "f"(x)); return y;
}
__device__ __forceinline__ void mma_tf32(float c[4], const uint32_t a[4], uint32_t b0, uint32_t b1) {
    asm volatile("mma.sync.aligned.m16n8k8.row.col.f32.tf32.tf32.f32 "
                 "{%0,%1,%2,%3}, {%4,%5,%6,%7}, {%8,%9}, {%0,%1,%2,%3};"
                 : "+f"(c[0]), "+f"(c[1]), "+f"(c[2]), "+f"(c[3])
                 : "r"(a[0]), "r"(a[1]), "r"(a[2]), "r"(a[3]), "r"(b0), "r"(b1));
}
__device__ __forceinline__ void cpa16(uint32_t dst, const void* src) {
    asm volatile("cp.async.ca.shared.global [%0], [%1], 16;" :: "r"(dst), "l"(src));
}
#define CPA_COMMIT() asm volatile("cp.async.commit_group;")

// ================= GroupNorm: stats + write normalized x (rna-tf32) =================
__global__ void __launch_bounds__(256) k_gnstats(const float* __restrict__ x,
                                                 const float* __restrict__ gw,
                                                 const float* __restrict__ gb)
{
    const int b = blockIdx.x >> 5;
    const int g = blockIdx.x & 31;
    const size_t base = ((size_t)(b * NC + g * CPG)) * NTOK;
    const float4* p4 = (const float4*)(x + base);
    float4* o4 = (float4*)(g_xn + base);
    float s = 0.f, s2 = 0.f;
    for (int i = threadIdx.x; i < 8192; i += 256) {
        float4 v = p4[i];
        s  += (v.x + v.y) + (v.z + v.w);
        s2 += v.x * v.x + v.y * v.y + v.z * v.z + v.w * v.w;
    }
    #pragma unroll
    for (int off = 16; off; off >>= 1) {
        s  += __shfl_xor_sync(0xffffffffu, s,  off);
        s2 += __shfl_xor_sync(0xffffffffu, s2, off);
    }
    __shared__ float ws[8], ws2[8];
    __shared__ float al8[CPG], be8[CPG];
    const int w = threadIdx.x >> 5;
    if ((threadIdx.x & 31) == 0) { ws[w] = s; ws2[w] = s2; }
    __syncthreads();
    if (threadIdx.x < CPG) {
        float t = 0.f, t2 = 0.f;
        #pragma unroll
        for (int i = 0; i < 8; i++) { t += ws[i]; t2 += ws2[i]; }
        float mean = t * (1.f / 32768.f);
        float var  = t2 * (1.f / 32768.f) - mean * mean;
        float sr = rsqrtf(var + 1e-5f);
        int c = g * CPG + threadIdx.x;
        float a = gw[c] * sr;
        al8[threadIdx.x] = a;
        be8[threadIdx.x] = gb[c] - mean * a;
    }
    __syncthreads();
    for (int i = threadIdx.x; i < 8192; i += 256) {
        int cl = i >> 10;
        float a = al8[cl], bb = be8[cl];
        float4 v = p4[i];
        o4[i] = make_float4(rtf(fmaf(v.x, a, bb)), rtf(fmaf(v.y, a, bb)),
                            rtf(fmaf(v.z, a, bb)), rtf(fmaf(v.w, a, bb)));
    }
}

// ================= pipelined tf32 GEMM =================
// C = A[m][k] * B[b][k][n] (+bias). B values already rna-tf32. A cvt'd at staging.
// 256 thr, 128m x 64n tile, k-chunk 32. B: cp.async double-buffer; A: reg prefetch.
template<int MTOT, int KTOT, bool ROUND, bool BIASED>
__global__ void __launch_bounds__(256) k_gemm(const float* __restrict__ A,
                                              const float* __restrict__ Bg,
                                              float* __restrict__ Cg,
                                              const float* __restrict__ bias)
{
    constexpr int NK = KTOT / 32;
    const int b  = blockIdx.z;
    const int m0 = blockIdx.y * 128;
    const int n0 = blockIdx.x * 64;
    __shared__ float As[128][36];
    __shared__ float Xs[2][32][72];
    const float* Bb = Bg + (size_t)b * KTOT * NTOK;
    const int tid = threadIdx.x, w = tid >> 5, lane = tid & 31;
    const int g = lane >> 2, t = lane & 3;
    const int wm = (w >> 1) * 32, wn = (w & 1) * 32;
    const uint32_t xsbase = (uint32_t)__cvta_generic_to_shared(&Xs[0][0][0]);
    const int kcA = tid >> 4, ncA = (tid & 15) << 2;
    const int kcB = kcA + 16;

    float4 ar[2][4];
    float acc[2][4][4] = {};

    cpa16(xsbase + kcA * 288 + ncA * 4, Bb + (size_t)kcA * NTOK + n0 + ncA);
    cpa16(xsbase + kcB * 288 + ncA * 4, Bb + (size_t)kcB * NTOK + n0 + ncA);
    CPA_COMMIT();
    #pragma unroll
    for (int i = 0; i < 4; i++) {
        int id = tid + 256 * i, m = id >> 3, c = (id & 7) << 2;
        ar[0][i] = *(const float4*)(A + (size_t)(m0 + m) * KTOT + c);
    }

    #pragma unroll
    for (int k = 0; k < NK; k++) {
        __syncthreads();
        #pragma unroll
        for (int i = 0; i < 4; i++) {
            int id = tid + 256 * i, m = id >> 3, c = (id & 7) << 2;
            float4 v = ar[k & 1][i];
            As[m][c] = rtf(v.x); As[m][c + 1] = rtf(v.y);
            As[m][c + 2] = rtf(v.z); As[m][c + 3] = rtf(v.w);
        }
        if (k + 1 < NK) {
            uint32_t bo = xsbase + ((k + 1) & 1) * 9216;
            cpa16(bo + kcA * 288 + ncA * 4, Bb + (size_t)((k + 1) * 32 + kcA) * NTOK + n0 + ncA);
            cpa16(bo + kcB * 288 + ncA * 4, Bb + (size_t)((k + 1) * 32 + kcB) * NTOK + n0 + ncA);
            CPA_COMMIT();
            #pragma unroll
            for (int i = 0; i < 4; i++) {
                int id = tid + 256 * i, m = id >> 3, c = (id & 7) << 2;
                ar[(k + 1) & 1][i] = *(const float4*)(A + (size_t)(m0 + m) * KTOT + (k + 1) * 32 + c);
            }
            asm volatile("cp.async.wait_group 1;");
        } else {
            asm volatile("cp.async.wait_group 0;");
        }
        __syncthreads();
        const float (*X)[72] = Xs[k & 1];
        #pragma unroll
        for (int ks = 0; ks < 4; ks++) {
            uint32_t a[2][4];
            #pragma unroll
            for (int mf = 0; mf < 2; mf++) {
                int r = wm + 16 * mf + g;
                a[mf][0] = __float_as_uint(As[r    ][8 * ks + t]);
                a[mf][1] = __float_as_uint(As[r + 8][8 * ks + t]);
                a[mf][2] = __float_as_uint(As[r    ][8 * ks + t + 4]);
                a[mf][3] = __float_as_uint(As[r + 8][8 * ks + t + 4]);
            }
            #pragma unroll
            for (int nf = 0; nf < 4; nf++) {
                uint32_t b0 = __float_as_uint(X[8 * ks + t    ][wn + 8 * nf + g]);
                uint32_t b1 = __float_as_uint(X[8 * ks + t + 4][wn + 8 * nf + g]);
                mma_tf32(acc[0][nf], a[0], b0, b1);
                mma_tf32(acc[1][nf], a[1], b0, b1);
            }
        }
    }

    float* Cb = Cg + (size_t)b * MTOT * NTOK;
    #pragma unroll
    for (int mf = 0; mf < 2; mf++) {
        int row = m0 + wm + 16 * mf + g;
        float bv0 = BIASED ? bias[row]     : 0.f;
        float bv8 = BIASED ? bias[row + 8] : 0.f;
        #pragma unroll
        for (int nf = 0; nf < 4; nf++) {
            int col = n0 + wn + 8 * nf + 2 * t;
            float v0 = acc[mf][nf][0] + bv0, v1 = acc[mf][nf][1] + bv0;
            float v2 = acc[mf][nf][2] + bv8, v3 = acc[mf][nf][3] + bv8;
            if (ROUND) { v0 = rtf(v0); v1 = rtf(v1); v2 = rtf(v2); v3 = rtf(v3); }
            *(float2*)(Cb + (size_t)row * NTOK + col)       = make_float2(v0, v1);
            *(float2*)(Cb + (size_t)(row + 8) * NTOK + col) = make_float2(v2, v3);
        }
    }
}

// ================= Flash attention: single-sync pipeline + SMEM P =================
// dyn SMEM layout (bytes):
//  Ks0 @0      32x72 f32 = 9216     Vs0 @9216  32x68 f32 = 8704
//  Ks1 @17920  9216                 Vs1 @27136 8704
//  P   @35840  8 warps x [16][36] f32 (2304 each) = 18432  -> total 54272
//  Qs  @0      128x36 f32 = 18432 (prologue/epilogue only; temporally aliased)
#define QT 128
#define KT 64
#define NTILES (NTOK / KT)
#define SMA_BYTES 54272
__global__ void __launch_bounds__(256, 2) k_attn()
{
    extern __shared__ __align__(16) char smraw[];
    float (*Qs)[36] = (float(*)[36])smraw;
    const uint32_t smbase = (uint32_t)__cvta_generic_to_shared(smraw);

    const int b  = blockIdx.z, h = blockIdx.y;
    const int n0 = blockIdx.x * QT;
    const int tid  = threadIdx.x;
    const int w    = tid >> 5;
    const int lane = tid & 31;
    const int grp  = lane >> 2;
    const int tg   = lane & 3;

    const float* qb = g_qkv + ((size_t)b * NQKV + h * DH) * NTOK;
    const float* kb = qb + (size_t)HID * NTOK;
    const float* vb = qb + (size_t)2 * HID * NTOK;

    const float qscale = 0.17677669529663687f * 1.4426950408889634f; // SCALE*log2(e)

    // ---- prologue: stage Q 128tok x 32f, build fragments ----
    #pragma unroll
    for (int i = 0; i < 4; i++) {
        int idx4 = tid + 256 * i;
        int f  = idx4 >> 5;
        int nc = (idx4 & 31) << 2;
        float4 v = *(const float4*)(qb + (size_t)f * NTOK + n0 + nc);
        Qs[nc + 0][f] = rtf(v.x * qscale);
        Qs[nc + 1][f] = rtf(v.y * qscale);
        Qs[nc + 2][f] = rtf(v.z * qscale);
        Qs[nc + 3][f] = rtf(v.w * qscale);
    }
    __syncthreads();
    const int qrow = w * 16 + grp;
    uint32_t qa[4][4];
    #pragma unroll
    for (int ks = 0; ks < 4; ks++) {
        qa[ks][0] = __float_as_uint(Qs[qrow    ][8 * ks + tg]);
        qa[ks][1] = __float_as_uint(Qs[qrow + 8][8 * ks + tg]);
        qa[ks][2] = __float_as_uint(Qs[qrow    ][8 * ks + tg + 4]);
        qa[ks][3] = __float_as_uint(Qs[qrow + 8][8 * ks + tg + 4]);
    }
    __syncthreads();   // all Q-frag reads done before K/V staging overwrites alias

    // staging coords: K rows stride 72 floats, V stride 68
    const int sf0 = tid >> 4;
    const int sj0 = (tid & 15) << 2;
    const int sf1 = sf0 + 16;
    const uint32_t kd0 = (uint32_t)(sf0 * 72 + sj0) * 4;
    const uint32_t kd1 = (uint32_t)(sf1 * 72 + sj0) * 4;
    const uint32_t vd0 = 9216u + (uint32_t)(sf0 * 68 + sj0) * 4;
    const uint32_t vd1 = 9216u + (uint32_t)(sf1 * 68 + sj0) * 4;
    float (*Pw)[36] = (float(*)[36])(smraw + 35840 + w * 2304);

    float o[4][4] = {};
    float m0r = -1e30f, m1r = -1e30f;
    float l0 = 0.f, l1 = 0.f;

    // prefetch tile 0 -> buf0
    cpa16(smbase + kd0, kb + (size_t)sf0 * NTOK + sj0);
    cpa16(smbase + kd1, kb + (size_t)sf1 * NTOK + sj0);
    cpa16(smbase + vd0, vb + (size_t)sf0 * NTOK + sj0);
    cpa16(smbase + vd1, vb + (size_t)sf1 * NTOK + sj0);
    CPA_COMMIT();

    for (int tIdx = 0; tIdx < NTILES; tIdx++) {
        const int cur = tIdx & 1;
        __syncthreads();   // everyone done reading buf[1-cur] (prev tile) + P safe
        if (tIdx + 1 < NTILES) {
            const uint32_t bo = smbase + (cur ? 0u : 17920u);
            const int jn = (tIdx + 1) * KT;
            cpa16(bo + kd0, kb + (size_t)sf0 * NTOK + jn + sj0);
            cpa16(bo + kd1, kb + (size_t)sf1 * NTOK + jn + sj0);
            cpa16(bo + vd0, vb + (size_t)sf0 * NTOK + jn + sj0);
            cpa16(bo + vd1, vb + (size_t)sf1 * NTOK + jn + sj0);
            CPA_COMMIT();
            asm volatile("cp.async.wait_group 1;");
        } else {
            asm volatile("cp.async.wait_group 0;");
        }

        const float (*Ks)[72] = (const float(*)[72])(smraw + cur * 17920);
        const float (*Vs)[68] = (const float(*)[68])(smraw + cur * 17920 + 9216);

        // ---- S = Q K^T (16q x 64k per warp) ----
        float sc[8][4];
        #pragma unroll
        for (int nt = 0; nt < 8; nt++) {
            sc[nt][0] = sc[nt][1] = sc[nt][2] = sc[nt][3] = 0.f;
            #pragma unroll
            for (int ks = 0; ks < 4; ks++) {
                uint32_t b0 = __float_as_uint(Ks[8 * ks + tg    ][8 * nt + grp]);
                uint32_t b1 = __float_as_uint(Ks[8 * ks + tg + 4][8 * nt + grp]);
                mma_tf32(sc[nt], qa[ks], b0, b1);
            }
        }

        // ---- online softmax (exp2 domain) ----
        float mt0 = -1e30f, mt1 = -1e30f;
        #pragma unroll
        for (int nt = 0; nt < 8; nt++) {
            mt0 = fmaxf(mt0, fmaxf(sc[nt][0], sc[nt][1]));
            mt1 = fmaxf(mt1, fmaxf(sc[nt][2], sc[nt][3]));
        }
        mt0 = fmaxf(mt0, __shfl_xor_sync(0xffffffffu, mt0, 1));
        mt0 = fmaxf(mt0, __shfl_xor_sync(0xffffffffu, mt0, 2));
        mt1 = fmaxf(mt1, __shfl_xor_sync(0xffffffffu, mt1, 1));
        mt1 = fmaxf(mt1, __shfl_xor_sync(0xffffffffu, mt1, 2));
        float mn0 = fmaxf(m0r, mt0), mn1 = fmaxf(m1r, mt1);
        float c0 = ex2(m0r - mn0), c1 = ex2(m1r - mn1);
        m0r = mn0; m1r = mn1;
        l0 *= c0; l1 *= c1;
        #pragma unroll
        for (int nf = 0; nf < 4; nf++) {
            o[nf][0] *= c0; o[nf][1] *= c0;
            o[nf][2] *= c1; o[nf][3] *= c1;
        }
        float rs0 = 0.f, rs1 = 0.f;
        #pragma unroll
        for (int nt = 0; nt < 8; nt++) {
            float p0 = ex2(sc[nt][0] - mn0);
            float p1 = ex2(sc[nt][1] - mn0);
            float p2 = ex2(sc[nt][2] - mn1);
            float p3 = ex2(sc[nt][3] - mn1);
            rs0 += p0 + p1; rs1 += p2 + p3;
            sc[nt][0] = p0; sc[nt][1] = p1; sc[nt][2] = p2; sc[nt][3] = p3;
        }
        rs0 += __shfl_xor_sync(0xffffffffu, rs0, 1);
        rs0 += __shfl_xor_sync(0xffffffffu, rs0, 2);
        rs1 += __shfl_xor_sync(0xffffffffu, rs1, 1);
        rs1 += __shfl_xor_sync(0xffffffffu, rs1, 2);
        l0 += rs0; l1 += rs1;

        // ---- O += P V : P via per-warp SMEM, two 32-key halves ----
        #pragma unroll
        for (int h2 = 0; h2 < 2; h2++) {
            #pragma unroll
            for (int ntl = 0; ntl < 4; ntl++) {
                int nt = 4 * h2 + ntl;
                *(float2*)&Pw[grp    ][8 * ntl + 2 * tg] = make_float2(sc[nt][0], sc[nt][1]);
                *(float2*)&Pw[grp + 8][8 * ntl + 2 * tg] = make_float2(sc[nt][2], sc[nt][3]);
            }
            __syncwarp();
            #pragma unroll
            for (int kkl = 0; kkl < 4; kkl++) {
                int kk = 4 * h2 + kkl;
                uint32_t pa[4];
                pa[0] = __float_as_uint(Pw[grp    ][8 * kkl + tg]);
                pa[1] = __float_as_uint(Pw[grp + 8][8 * kkl + tg]);
                pa[2] = __float_as_uint(Pw[grp    ][8 * kkl + tg + 4]);
                pa[3] = __float_as_uint(Pw[grp + 8][8 * kkl + tg + 4]);
                #pragma unroll
                for (int nf = 0; nf < 4; nf++) {
                    uint32_t b0 = __float_as_uint(Vs[8 * nf + grp][8 * kk + tg]);
                    uint32_t b1 = __float_as_uint(Vs[8 * nf + grp][8 * kk + tg + 4]);
                    mma_tf32(o[nf], pa, b0, b1);
                }
            }
            __syncwarp();   // reads done before next-half store overwrites
        }
    }
    __syncthreads();   // final tile reads done; Qs alias region free

    // ---- epilogue: normalize, rna-round, stage via Qs, coalesced write ----
    float inv0 = 1.0f / l0, inv1 = 1.0f / l1;
    #pragma unroll
    for (int nf = 0; nf < 4; nf++) {
        Qs[qrow    ][8 * nf + 2 * tg    ] = rtf(o[nf][0] * inv0);
        Qs[qrow    ][8 * nf + 2 * tg + 1] = rtf(o[nf][1] * inv0);
        Qs[qrow + 8][8 * nf + 2 * tg    ] = rtf(o[nf][2] * inv1);
        Qs[qrow + 8][8 * nf + 2 * tg + 1] = rtf(o[nf][3] * inv1);
    }
    __syncthreads();
    float* ob = g_att + ((size_t)b * HID + h * DH) * NTOK;
    #pragma unroll
    for (int i = 0; i < 4; i++) {
        int idx4 = tid + 256 * i;
        int f  = idx4 >> 5;
        int nc = (idx4 & 31) << 2;
        *(float4*)(ob + (size_t)f * NTOK + n0 + nc) =
            make_float4(Qs[nc + 0][f], Qs[nc + 1][f], Qs[nc + 2][f], Qs[nc + 3][f]);
    }
}

// ================= launch =================
extern "C" void kernel_launch(void* const* d_in, const int* in_sizes, int n_in,
                              void* d_out, int out_size)
{
    const float* x    = (const float*)d_in[0];
    const float* gw   = (const float*)d_in[1];
    const float* gb   = (const float*)d_in[2];
    const float* wqkv = (const float*)d_in[3];
    const float* wout = (const float*)d_in[4];
    const float* bout = (const float*)d_in[5];
    float* out = (float*)d_out;

    float* qkv = nullptr; cudaGetSymbolAddress((void**)&qkv, g_qkv);
    float* att = nullptr; cudaGetSymbolAddress((void**)&att, g_att);
    float* xn  = nullptr; cudaGetSymbolAddress((void**)&xn,  g_xn);

    cudaFuncSetAttribute(k_attn, cudaFuncAttributeMaxDynamicSharedMemorySize, SMA_BYTES);

    k_gnstats<<<NB * 32, 256>>>(x, gw, gb);
    k_gemm<NQKV, NC, true, false><<<dim3(64, 3, NB), 256>>>(wqkv, xn, qkv, nullptr);
    k_attn<<<dim3(NTOK / QT, NHEAD, NB), 256, SMA_BYTES>>>();
    k_gemm<NC, HID, false, true><<<dim3(64, 2, NB), 256>>>(wout, att, out, bout);
}